// round 16
// baseline (speedup 1.0000x reference)
#include <cuda_runtime.h>
#include <cstdint>

#define IN  8192
#define OUT 8192
#define RW  1024               // packed int32 word-rows (IN/8)
#define KSPLIT 2
#define RH  (RW / KSPLIT)      // 512 word-rows per CTA
#define TPB 256                // 8 warps
#define OPB 32                 // outputs per tile -> line-aligned 128B row segments
#define ROWS_IT 32             // rows per iteration (8 warps x 4)
#define NIT (RH / ROWS_IT)     // 16 iterations
#define DEPTH 4                // cp.async ring stages
#define XSCALE 2048.0f
#define NTILE (OUT / OPB)      // 256 output tiles

// Cross-CTA state (no allocation allowed -> __device__ globals; zero-init)
__device__ int      g_part[KSPLIT][OUT];
__device__ float    g_sx[KSPLIT];
__device__ unsigned g_cnt[NTILE];

// dp2a dequant: ne = w & 0x0F0F0F0F -> bytes (n0,n2,n4,n6),
//               no = (w>>4) & 0x0F0F0F0F -> bytes (n1,n3,n5,n7).
// x row stored as 4 packed int16x2: (x0,x2),(x4,x6),(x1,x3),(x5,x7).
__device__ __forceinline__ void dqw(unsigned w, const uint4& xq, int& acc) {
    unsigned ne = w & 0x0F0F0F0Fu;
    unsigned no = (w >> 4) & 0x0F0F0F0Fu;
    asm("dp2a.lo.s32.u32 %0, %1, %2, %0;" : "+r"(acc) : "r"(xq.x), "r"(ne)); // x0n0+x2n2
    asm("dp2a.hi.s32.u32 %0, %1, %2, %0;" : "+r"(acc) : "r"(xq.y), "r"(ne)); // x4n4+x6n6
    asm("dp2a.lo.s32.u32 %0, %1, %2, %0;" : "+r"(acc) : "r"(xq.z), "r"(no)); // x1n1+x3n3
    asm("dp2a.hi.s32.u32 %0, %1, %2, %0;" : "+r"(acc) : "r"(xq.w), "r"(no)); // x5n5+x7n7
}

__device__ __forceinline__ void cp16(void* sdst, const void* gsrc) {
    unsigned s = (unsigned)__cvta_generic_to_shared(sdst);
    asm volatile("cp.async.cg.shared.global [%0], [%1], 16;\n" :: "r"(s), "l"(gsrc));
}
#define CP_COMMIT() asm volatile("cp.async.commit_group;\n" ::: "memory")
#define CP_WAIT(n)  asm volatile("cp.async.wait_group %0;\n" :: "n"(n) : "memory")

__global__ __launch_bounds__(TPB, 6)
void qmv_kernel(const float* __restrict__ x, const int* __restrict__ qw,
                const float* __restrict__ scales, const float* __restrict__ zeros,
                const float* __restrict__ bias, float* __restrict__ out) {
    __shared__ uint4    ring[DEPTH][TPB];   // 16 KB weight staging
    __shared__ unsigned xs[RH * 4];         // 8 KB quantized x (this K-half)
    __shared__ int      red[ROWS_IT][OPB];  // 4 KB
    __shared__ int      r2[8][OPB];         // 1 KB
    __shared__ float    wsums[8];
    __shared__ int      slast;

    const int tid  = threadIdx.x;
    const int lane = tid & 31;
    const int w    = tid >> 5;
    const int oq   = lane & 7;        // output quad 0..7 (8 x 4 = 32 outputs)
    const int rw   = lane >> 3;       // row-within-warp 0..3
    const int bx   = blockIdx.x;
    const int ky   = blockIdx.y;
    const int rloc = w * 4 + rw;      // local row 0..31 (per iteration)

    // ---- weight pointer: warp's 32 lanes cover 4 consecutive rows x 128B,
    //      i.e. 4 FULL cache lines per warp access (nL = 4) ----
    const char* qg = reinterpret_cast<const char*>(qw) +
                     ((size_t)(ky * RH + rloc) * OUT + (size_t)bx * OPB) * 4 + oq * 16;
    const size_t qstep = (size_t)ROWS_IT * OUT * 4;   // 1 MB per iteration

    #pragma unroll
    for (int s = 0; s < DEPTH - 1; s++) {
        cp16(&ring[s][tid], qg + (size_t)s * qstep);
        CP_COMMIT();
    }

    // ---- quantize this half's x -> int16 pairs in smem; exact fp32 Sum(x) ----
    float sp = 0.f;
    const float4* xg = reinterpret_cast<const float4*>(x) + ky * (RH * 2);
    #pragma unroll
    for (int j = 0; j < 4; j++) {
        int i = tid + j * TPB;            // float4 index 0..1023 (coalesced)
        float4 v = xg[i];
        sp += (v.x + v.y) + (v.z + v.w);
        int q0 = __float2int_rn(v.x * XSCALE);
        int q1 = __float2int_rn(v.y * XSCALE);
        int q2 = __float2int_rn(v.z * XSCALE);
        int q3 = __float2int_rn(v.w * XSCALE);
        unsigned even = ((unsigned)q0 & 0xFFFFu) | ((unsigned)q2 << 16);
        unsigned odd  = ((unsigned)q1 & 0xFFFFu) | ((unsigned)q3 << 16);
        int row = i >> 1;
        int base = row * 4 + (i & 1);     // even float4 -> slots 0,2; odd -> 1,3
        xs[base]     = even;              // (x0,x2) or (x4,x6)
        xs[base + 2] = odd;               // (x1,x3) or (x5,x7)
    }
    #pragma unroll
    for (int o = 16; o > 0; o >>= 1)
        sp += __shfl_down_sync(0xffffffffu, sp, o);
    if (lane == 0) wsums[w] = sp;
    __syncthreads();

    // ---- main loop: 4 outputs per thread, rows rloc + 32*i (this half) ----
    int c0 = 0, c1 = 0, c2 = 0, c3 = 0;

    #pragma unroll
    for (int i = 0; i < NIT; i++) {
        if (i + DEPTH - 1 < NIT)
            cp16(&ring[(i + DEPTH - 1) & (DEPTH - 1)][tid],
                 qg + (size_t)(i + DEPTH - 1) * qstep);
        CP_COMMIT();
        CP_WAIT(DEPTH - 1);   // stage i ready

        uint4 wv = ring[i & (DEPTH - 1)][tid];
        uint4 xq = *reinterpret_cast<const uint4*>(&xs[4 * (rloc + i * ROWS_IT)]);
        dqw(wv.x, xq, c0);
        dqw(wv.y, xq, c1);
        dqw(wv.z, xq, c2);
        dqw(wv.w, xq, c3);
    }

    *reinterpret_cast<int4*>(&red[rloc][oq * 4]) = make_int4(c0, c1, c2, c3);
    __syncthreads();

    // ---- integer reduction over 32 row-groups (exact, deterministic) ----
    {
        int o = tid & 31, seg = tid >> 5;   // 8 segs x 4 row-groups
        int s = 0;
        #pragma unroll
        for (int j = 0; j < 4; j++) s += red[seg * 4 + j][o];
        r2[seg][o] = s;
    }
    __syncthreads();

    if (tid < OPB) {
        int isum = 0;
        #pragma unroll
        for (int s = 0; s < 8; s++) isum += r2[s][tid];
        g_part[ky][bx * OPB + tid] = isum;
        if (tid == 0) {
            float sx = 0.f;
            #pragma unroll
            for (int i = 0; i < 8; i++) sx += wsums[i];
            g_sx[ky] = sx;   // every bx writes the same value -> deterministic
        }
    }
    __syncthreads();

    // ---- last CTA per output tile combines (integer-exact, deterministic) ----
    __threadfence();
    if (tid == 0)
        slast = (atomicAdd(&g_cnt[bx], 1u) == KSPLIT - 1);
    __syncthreads();
    if (slast) {
        if (tid < OPB) {
            int o = bx * OPB + tid;
            float dot = (float)(g_part[0][o] + g_part[1][o]) * (1.0f / XSCALE);
            float sx  = g_sx[0] + g_sx[1];
            out[o] = bias[o] + scales[o] * dot - zeros[o] * sx;
        }
        if (tid == 0) g_cnt[bx] = 0u;   // reset for next graph replay
    }
}

extern "C" void kernel_launch(void* const* d_in, const int* in_sizes, int n_in,
                              void* d_out, int out_size) {
    const float* x      = (const float*)d_in[0];
    const int*   qw     = (const int*)d_in[1];
    const float* scales = (const float*)d_in[2];
    const float* zeros  = (const float*)d_in[3];
    const float* bias   = (const float*)d_in[4];
    float* out = (float*)d_out;

    dim3 grid(NTILE, KSPLIT);   // 256 x 2 = 512 CTAs
    qmv_kernel<<<grid, TPB>>>(x, qw, scales, zeros, bias, out);
}

// round 17
// speedup vs baseline: 1.2627x; 1.2627x over previous
#include <cuda_runtime.h>
#include <cstdint>

#define IN 8192
#define OUT 8192
#define RW 1024            // packed int32 rows (IN/8)
#define TPB 256            // 8 warps
#define OPB 16             // outputs per block -> grid 512
#define NRG 64             // concurrent word-rows per CTA
#define NIT (RW / NRG)     // 16 iterations per thread
#define DEPTH 8            // cp.async ring stages (distance-7 prefetch > DRAM lat)
#define XSCALE 2048.0f     // x int16 quantization scale

// dp2a dequant: ne = w & 0x0F0F0F0F -> bytes (n0,n2,n4,n6),
//               no = (w>>4) & 0x0F0F0F0F -> bytes (n1,n3,n5,n7).
// x row stored as 4 packed int16x2: (x0,x2),(x4,x6),(x1,x3),(x5,x7).
// 4 dp2a accumulate all 8 x*v products, integer-exact.
__device__ __forceinline__ void dqw(unsigned w, const uint4& xq, int& acc) {
    unsigned ne = w & 0x0F0F0F0Fu;
    unsigned no = (w >> 4) & 0x0F0F0F0Fu;
    asm("dp2a.lo.s32.u32 %0, %1, %2, %0;" : "+r"(acc) : "r"(xq.x), "r"(ne)); // x0n0+x2n2
    asm("dp2a.hi.s32.u32 %0, %1, %2, %0;" : "+r"(acc) : "r"(xq.y), "r"(ne)); // x4n4+x6n6
    asm("dp2a.lo.s32.u32 %0, %1, %2, %0;" : "+r"(acc) : "r"(xq.z), "r"(no)); // x1n1+x3n3
    asm("dp2a.hi.s32.u32 %0, %1, %2, %0;" : "+r"(acc) : "r"(xq.w), "r"(no)); // x5n5+x7n7
}

__device__ __forceinline__ void cp16(void* sdst, const void* gsrc) {
    unsigned s = (unsigned)__cvta_generic_to_shared(sdst);
    asm volatile("cp.async.cg.shared.global [%0], [%1], 16;\n" :: "r"(s), "l"(gsrc));
}
#define CP_COMMIT() asm volatile("cp.async.commit_group;\n" ::: "memory")
#define CP_WAIT(n)  asm volatile("cp.async.wait_group %0;\n" :: "n"(n) : "memory")

__global__ __launch_bounds__(TPB, 4)
void qmv_kernel(const float* __restrict__ x, const int* __restrict__ qw,
                const float* __restrict__ scales, const float* __restrict__ zeros,
                const float* __restrict__ bias, float* __restrict__ out) {
    __shared__ uint4    ring[DEPTH][TPB];   // 32 KB weight staging
    __shared__ unsigned xs[RW * 4];         // 16 KB quantized x
    __shared__ int      red[NRG][OPB];      // 4 KB
    __shared__ int      r2[8][OPB];
    __shared__ float    wsums[8];

    const int tid  = threadIdx.x;
    const int lane = tid & 31;
    const int w    = tid >> 5;
    const int og   = lane & 3;                 // output quad 0..3
    const int rg   = (w << 3) | (lane >> 2);   // word-row group 0..63
    const int bx   = blockIdx.x;

    // ---- start the weight pipeline immediately ----
    const char* qg = reinterpret_cast<const char*>(qw) +
                     ((size_t)rg * OUT + (size_t)bx * OPB) * 4 + og * 16;
    const size_t qstep = (size_t)NRG * OUT * 4;

    #pragma unroll
    for (int s = 0; s < DEPTH - 1; s++) {
        cp16(&ring[s][tid], qg + (size_t)s * qstep);
        CP_COMMIT();
    }

    // ---- quantize x -> int16 pairs in smem; exact fp32 Sum(x) ----
    float sp = 0.f;
    const float4* xg = reinterpret_cast<const float4*>(x);
    #pragma unroll
    for (int j = 0; j < 8; j++) {
        int i = tid + j * TPB;            // float4 index (coalesced)
        float4 v = xg[i];
        sp += (v.x + v.y) + (v.z + v.w);
        int q0 = __float2int_rn(v.x * XSCALE);
        int q1 = __float2int_rn(v.y * XSCALE);
        int q2 = __float2int_rn(v.z * XSCALE);
        int q3 = __float2int_rn(v.w * XSCALE);
        unsigned even = ((unsigned)q0 & 0xFFFFu) | ((unsigned)q2 << 16);
        unsigned odd  = ((unsigned)q1 & 0xFFFFu) | ((unsigned)q3 << 16);
        int row = i >> 1;
        int base = row * 4 + (i & 1);     // even half -> slots 0,2; odd -> 1,3
        xs[base]     = even;              // (x0,x2) or (x4,x6)
        xs[base + 2] = odd;               // (x1,x3) or (x5,x7)
    }
    #pragma unroll
    for (int o = 16; o > 0; o >>= 1)
        sp += __shfl_down_sync(0xffffffffu, sp, o);
    if (lane == 0) wsums[w] = sp;
    __syncthreads();

    // ---- main loop: 4 outputs per thread, rows rg + 64*i, int-exact dp2a ----
    int c0 = 0, c1 = 0, c2 = 0, c3 = 0;

    #pragma unroll 4
    for (int i = 0; i < NIT; i++) {
        if (i + DEPTH - 1 < NIT)
            cp16(&ring[(i + DEPTH - 1) & (DEPTH - 1)][tid],
                 qg + (size_t)(i + DEPTH - 1) * qstep);
        CP_COMMIT();
        CP_WAIT(DEPTH - 1);   // stage i ready (issued 7 iterations ago)

        uint4 wv = ring[i & (DEPTH - 1)][tid];
        int r = rg + (i << 6);
        uint4 xq = *reinterpret_cast<const uint4*>(&xs[4 * r]);
        dqw(wv.x, xq, c0);
        dqw(wv.y, xq, c1);
        dqw(wv.z, xq, c2);
        dqw(wv.w, xq, c3);
    }

    *reinterpret_cast<int4*>(&red[rg][og * 4]) = make_int4(c0, c1, c2, c3);
    __syncthreads();

    // ---- integer reduction over 64 row-groups (exact, deterministic) ----
    if (tid < 128) {
        int o = tid & 15, seg = tid >> 4;   // 8 segs x 8 row-groups
        int s = 0;
        #pragma unroll
        for (int j = 0; j < 8; j++) s += red[seg * 8 + j][o];
        r2[seg][o] = s;
    }
    __syncthreads();

    if (tid < OPB) {
        int isum = 0;
        #pragma unroll
        for (int s = 0; s < 8; s++) isum += r2[s][tid];
        float dot = (float)isum * (1.0f / XSCALE);
        float sx = 0.f;
        #pragma unroll
        for (int i = 0; i < 8; i++) sx += wsums[i];
        int o = bx * OPB + tid;
        out[o] = bias[o] + scales[o] * dot - zeros[o] * sx;
    }
}

extern "C" void kernel_launch(void* const* d_in, const int* in_sizes, int n_in,
                              void* d_out, int out_size) {
    const float* x      = (const float*)d_in[0];
    const int*   qw     = (const int*)d_in[1];
    const float* scales = (const float*)d_in[2];
    const float* zeros  = (const float*)d_in[3];
    const float* bias   = (const float*)d_in[4];
    float* out = (float*)d_out;

    qmv_kernel<<<OUT / OPB, TPB>>>(x, qw, scales, zeros, bias, out);
}